// round 3
// baseline (speedup 1.0000x reference)
#include <cuda_runtime.h>
#include <cstdint>

// Problem constants (fixed shapes from setup_inputs)
#define BATCH   16
#define CHX     256
#define NPOS    170
#define TT      64
#define CIN     512
#define COUT    512
#define NHEAD   8
#define HDIM    64
#define BN      (BATCH*NPOS)      // 2720
#define NTSTR   (NPOS*TT)         // 10880 = channel stride in [B,C,N,T]
#define QKV_ELEMS (BN*NHEAD*TT*HDIM)   // 89,128,960

// Scratch (device globals — no allocation allowed)
__device__ float g_q[QKV_ELEMS];
__device__ float g_k[QKV_ELEMS];
__device__ float g_v[QKV_ELEMS];
__device__ float g_o[QKV_ELEMS];   // [token(174080)][512] row-major

// ---------------------------------------------------------------------------
__device__ __forceinline__ uint32_t f2tf32(float f) {
    uint32_t r;
    asm("cvt.rna.tf32.f32 %0, %1;" : "=r"(r) : "f"(f));
    return r;
}

__device__ __forceinline__ void mma_tf32(float* d, const uint32_t* a, const uint32_t* b) {
    asm volatile(
        "mma.sync.aligned.m16n8k8.row.col.f32.tf32.tf32.f32 "
        "{%0,%1,%2,%3},{%4,%5,%6,%7},{%8,%9},{%0,%1,%2,%3};\n"
        : "+f"(d[0]), "+f"(d[1]), "+f"(d[2]), "+f"(d[3])
        : "r"(a[0]), "r"(a[1]), "r"(a[2]), "r"(a[3]),
          "r"(b[0]), "r"(b[1]));
}

// ---------------------------------------------------------------------------
// Kernel 1: QKV projection.
// grid (BN/2 = 1360, 12), block 256.
// CTA: Mtile=128 tokens (two (b,n) blocks of 64 t each), Ntile=128 output
// channels within one of {Wq,Wk,Wv}. K=512, Ktile=32.
// Output layout: buf[(bn*8+h)*64*64 + t*64 + dd]  (per-head [T,d] tiles).
// ---------------------------------------------------------------------------
__global__ __launch_bounds__(256, 2)
void qkv_kernel(const float* __restrict__ x, const float* __restrict__ tem,
                const float* __restrict__ Wq, const float* __restrict__ bq,
                const float* __restrict__ Wk, const float* __restrict__ bk,
                const float* __restrict__ Wv, const float* __restrict__ bv)
{
    __shared__ uint32_t As[128 * 36];
    __shared__ uint32_t Bs[128 * 36];
    __shared__ int rowOff[128];

    const int tid  = threadIdx.x;
    const int bn0  = blockIdx.x * 2;
    const int y    = blockIdx.y;

    const float* W;  const float* bias;  float* outBuf;
    const int mat = y >> 2;            // 0:q 1:k 2:v
    const int r0  = (y & 3) * 128;     // output-channel base within matrix
    if (mat == 0)      { W = Wq; bias = bq; outBuf = g_q; }
    else if (mat == 1) { W = Wk; bias = bk; outBuf = g_k; }
    else               { W = Wv; bias = bv; outBuf = g_v; }

    if (tid < 128) {
        int bn = bn0 + (tid >> 6);
        int b  = bn / NPOS, n = bn % NPOS;
        rowOff[tid] = b * (CHX * NTSTR) + n * TT + (tid & 63);
    }
    __syncthreads();

    const int lane = tid & 31, wid = tid >> 5;
    const int wm = wid & 3, wn = wid >> 2;
    const int g = lane >> 2, t4 = lane & 3;
    const int mbase = wm * 32, nbase = wn * 64;

    float acc[2][8][4];
#pragma unroll
    for (int mi = 0; mi < 2; mi++)
#pragma unroll
        for (int ni = 0; ni < 8; ni++)
#pragma unroll
            for (int j = 0; j < 4; j++) acc[mi][ni][j] = 0.f;

    for (int k0 = 0; k0 < CIN; k0 += 32) {
        // A tile: 128 rows (tokens) x 32 k (channels), coalesced over t
#pragma unroll
        for (int j = 0; j < 16; j++) {
            int i = tid + j * 256;
            int k = i >> 7, r = i & 127;
            int c = k0 + k;
            const float* src = (c < CHX) ? x : tem;
            float v = __ldg(&src[rowOff[r] + (c & 255) * NTSTR]);
            As[r * 36 + k] = f2tf32(v);
        }
        // B tile: 128 output rows x 32 k, coalesced over k
#pragma unroll
        for (int j = 0; j < 16; j++) {
            int nn = (tid >> 5) + j * 8;
            int k  = tid & 31;
            float v = __ldg(&W[(r0 + nn) * CIN + k0 + k]);
            Bs[nn * 36 + k] = f2tf32(v);
        }
        __syncthreads();

#pragma unroll
        for (int ks = 0; ks < 32; ks += 8) {
            uint32_t af[2][4], bf[8][2];
#pragma unroll
            for (int mi = 0; mi < 2; mi++) {
                int r = mbase + mi * 16 + g;
                af[mi][0] = As[r * 36 + ks + t4];
                af[mi][1] = As[(r + 8) * 36 + ks + t4];
                af[mi][2] = As[r * 36 + ks + t4 + 4];
                af[mi][3] = As[(r + 8) * 36 + ks + t4 + 4];
            }
#pragma unroll
            for (int ni = 0; ni < 8; ni++) {
                int c = nbase + ni * 8 + g;
                bf[ni][0] = Bs[c * 36 + ks + t4];
                bf[ni][1] = Bs[c * 36 + ks + t4 + 4];
            }
#pragma unroll
            for (int mi = 0; mi < 2; mi++)
#pragma unroll
                for (int ni = 0; ni < 8; ni++)
                    mma_tf32(acc[mi][ni], af[mi], bf[ni]);
        }
        __syncthreads();
    }

    // Epilogue: bias + store into per-head [T,d] tiles
#pragma unroll
    for (int mi = 0; mi < 2; mi++) {
        int rloc = mbase + mi * 16 + g;
        int bn = bn0 + (rloc >> 6);
        int t  = rloc & 63;
        int tileBase = (bn * NHEAD) * (TT * HDIM);
#pragma unroll
        for (int ni = 0; ni < 8; ni++) {
            int j = nbase + ni * 8 + 2 * t4;
            int o = r0 + j;                     // 0..511 within matrix
            int h = o >> 6, dd = o & 63;
            float b0 = bias[o], b1 = bias[o + 1];
            float2 v0 = make_float2(acc[mi][ni][0] + b0, acc[mi][ni][1] + b1);
            float2 v1 = make_float2(acc[mi][ni][2] + b0, acc[mi][ni][3] + b1);
            int base = tileBase + h * (TT * HDIM) + dd;
            *(float2*)&outBuf[base + t * HDIM]       = v0;
            *(float2*)&outBuf[base + (t + 8) * HDIM] = v1;
        }
    }
}

// ---------------------------------------------------------------------------
// Kernel 2: causal attention per (bn, head) tile: [64,64] Q,K,V.
// grid 21760, block 128 (4 warps, each owns 16 rows x 64 cols).
// S = QK^T/8 -> mask(-32767) -> softmax -> O = P V -> g_o[token][h*64+dd]
// ---------------------------------------------------------------------------
__global__ __launch_bounds__(128, 4)
void attn_kernel()
{
    __shared__ uint32_t Qs[64 * 68];   // Q, then reused for P
    __shared__ uint32_t Ks[64 * 68];   // K, then reused for V^T

    const int tid = threadIdx.x;
    const int lane = tid & 31, wid = tid >> 5;
    const int g = lane >> 2, t4 = lane & 3;
    const int bh = blockIdx.x;
    const int base = bh * (TT * HDIM);

    for (int i = tid; i < TT * HDIM; i += 128) {
        int t = i >> 6, d = i & 63;
        Qs[t * 68 + d] = f2tf32(g_q[base + i]);
        Ks[t * 68 + d] = f2tf32(g_k[base + i]);
    }
    __syncthreads();

    const int rbase = wid * 16;
    float s[8][4];
#pragma unroll
    for (int ni = 0; ni < 8; ni++)
#pragma unroll
        for (int j = 0; j < 4; j++) s[ni][j] = 0.f;

#pragma unroll
    for (int ks = 0; ks < 64; ks += 8) {
        uint32_t af[4];
        int r = rbase + g;
        af[0] = Qs[r * 68 + ks + t4];
        af[1] = Qs[(r + 8) * 68 + ks + t4];
        af[2] = Qs[r * 68 + ks + t4 + 4];
        af[3] = Qs[(r + 8) * 68 + ks + t4 + 4];
#pragma unroll
        for (int ni = 0; ni < 8; ni++) {
            uint32_t bf[2];
            bf[0] = Ks[(ni * 8 + g) * 68 + ks + t4];
            bf[1] = Ks[(ni * 8 + g) * 68 + ks + t4 + 4];
            mma_tf32(s[ni], af, bf);
        }
    }
    __syncthreads();   // all warps done reading Qs/Ks

    // softmax on rows rA = rbase+g (regs 0,1) and rB = rA+8 (regs 2,3)
    const int rA = rbase + g, rB = rA + 8;
    float mx0 = -1e30f, mx1 = -1e30f;
#pragma unroll
    for (int ni = 0; ni < 8; ni++) {
        int c0 = ni * 8 + 2 * t4, c1 = c0 + 1;
        s[ni][0] = (c0 <= rA) ? s[ni][0] * 0.125f : -32767.0f;
        s[ni][1] = (c1 <= rA) ? s[ni][1] * 0.125f : -32767.0f;
        s[ni][2] = (c0 <= rB) ? s[ni][2] * 0.125f : -32767.0f;
        s[ni][3] = (c1 <= rB) ? s[ni][3] * 0.125f : -32767.0f;
        mx0 = fmaxf(mx0, fmaxf(s[ni][0], s[ni][1]));
        mx1 = fmaxf(mx1, fmaxf(s[ni][2], s[ni][3]));
    }
    mx0 = fmaxf(mx0, __shfl_xor_sync(0xffffffffu, mx0, 1));
    mx0 = fmaxf(mx0, __shfl_xor_sync(0xffffffffu, mx0, 2));
    mx1 = fmaxf(mx1, __shfl_xor_sync(0xffffffffu, mx1, 1));
    mx1 = fmaxf(mx1, __shfl_xor_sync(0xffffffffu, mx1, 2));

    float sm0 = 0.f, sm1 = 0.f;
#pragma unroll
    for (int ni = 0; ni < 8; ni++) {
        s[ni][0] = __expf(s[ni][0] - mx0); sm0 += s[ni][0];
        s[ni][1] = __expf(s[ni][1] - mx0); sm0 += s[ni][1];
        s[ni][2] = __expf(s[ni][2] - mx1); sm1 += s[ni][2];
        s[ni][3] = __expf(s[ni][3] - mx1); sm1 += s[ni][3];
    }
    sm0 += __shfl_xor_sync(0xffffffffu, sm0, 1);
    sm0 += __shfl_xor_sync(0xffffffffu, sm0, 2);
    sm1 += __shfl_xor_sync(0xffffffffu, sm1, 1);
    sm1 += __shfl_xor_sync(0xffffffffu, sm1, 2);
    float inv0 = 1.f / sm0, inv1 = 1.f / sm1;

    // P -> Qs
#pragma unroll
    for (int ni = 0; ni < 8; ni++) {
        int c0 = ni * 8 + 2 * t4;
        Qs[rA * 68 + c0]     = f2tf32(s[ni][0] * inv0);
        Qs[rA * 68 + c0 + 1] = f2tf32(s[ni][1] * inv0);
        Qs[rB * 68 + c0]     = f2tf32(s[ni][2] * inv1);
        Qs[rB * 68 + c0 + 1] = f2tf32(s[ni][3] * inv1);
    }
    // V^T -> Ks  (Ks[d][sidx])
    for (int i = tid; i < TT * HDIM; i += 128) {
        int sidx = i >> 6, d = i & 63;
        Ks[d * 68 + sidx] = f2tf32(g_v[base + i]);
    }
    __syncthreads();

    // O = P @ V
    float o[8][4];
#pragma unroll
    for (int ni = 0; ni < 8; ni++)
#pragma unroll
        for (int j = 0; j < 4; j++) o[ni][j] = 0.f;

#pragma unroll
    for (int ks = 0; ks < 64; ks += 8) {
        uint32_t af[4];
        int r = rbase + g;
        af[0] = Qs[r * 68 + ks + t4];
        af[1] = Qs[(r + 8) * 68 + ks + t4];
        af[2] = Qs[r * 68 + ks + t4 + 4];
        af[3] = Qs[(r + 8) * 68 + ks + t4 + 4];
#pragma unroll
        for (int ni = 0; ni < 8; ni++) {
            uint32_t bf[2];
            bf[0] = Ks[(ni * 8 + g) * 68 + ks + t4];
            bf[1] = Ks[(ni * 8 + g) * 68 + ks + t4 + 4];
            mma_tf32(o[ni], af, bf);
        }
    }

    // store: g_o[(bn*64+t)*512 + h*64 + dd]
    const int bn = bh >> 3, h = bh & 7;
    float* ob = g_o + bn * (TT * COUT) + h * HDIM;
#pragma unroll
    for (int ni = 0; ni < 8; ni++) {
        int dd = ni * 8 + 2 * t4;
        *(float2*)&ob[rA * COUT + dd] = make_float2(o[ni][0], o[ni][1]);
        *(float2*)&ob[rB * COUT + dd] = make_float2(o[ni][2], o[ni][3]);
    }
}

// ---------------------------------------------------------------------------
// Kernel 3: output projection + bias + ReLU, back to [B,512,N,T].
// grid (1360, 4), block 256. Mtile=128 tokens, Ntile=128 outputs, K=512.
// ---------------------------------------------------------------------------
__global__ __launch_bounds__(256, 2)
void out_kernel(const float* __restrict__ Wo, const float* __restrict__ bo,
                float* __restrict__ out)
{
    __shared__ uint32_t As[128 * 36];
    __shared__ uint32_t Bs[128 * 36];
    __shared__ int outOff[128];

    const int tid = threadIdx.x;
    const int m0  = blockIdx.x * 128;
    const int r0  = blockIdx.y * 128;

    if (tid < 128) {
        int token = m0 + tid;
        int bn = token >> 6;
        int b = bn / NPOS, n = bn % NPOS;
        outOff[tid] = (b * COUT * NPOS + n) * TT + (token & 63);
    }
    __syncthreads();

    const int lane = tid & 31, wid = tid >> 5;
    const int wm = wid & 3, wn = wid >> 2;
    const int g = lane >> 2, t4 = lane & 3;
    const int mbase = wm * 32, nbase = wn * 64;

    float acc[2][8][4];
#pragma unroll
    for (int mi = 0; mi < 2; mi++)
#pragma unroll
        for (int ni = 0; ni < 8; ni++)
#pragma unroll
            for (int j = 0; j < 4; j++) acc[mi][ni][j] = 0.f;

    for (int k0 = 0; k0 < COUT; k0 += 32) {
#pragma unroll
        for (int j = 0; j < 16; j++) {
            int r = (tid >> 5) + j * 8;
            int k = tid & 31;
            As[r * 36 + k] = f2tf32(g_o[(m0 + r) * COUT + k0 + k]);
        }
#pragma unroll
        for (int j = 0; j < 16; j++) {
            int nn = (tid >> 5) + j * 8;
            int k  = tid & 31;
            Bs[nn * 36 + k] = f2tf32(__ldg(&Wo[(r0 + nn) * COUT + k0 + k]));
        }
        __syncthreads();

#pragma unroll
        for (int ks = 0; ks < 32; ks += 8) {
            uint32_t af[2][4], bf[8][2];
#pragma unroll
            for (int mi = 0; mi < 2; mi++) {
                int r = mbase + mi * 16 + g;
                af[mi][0] = As[r * 36 + ks + t4];
                af[mi][1] = As[(r + 8) * 36 + ks + t4];
                af[mi][2] = As[r * 36 + ks + t4 + 4];
                af[mi][3] = As[(r + 8) * 36 + ks + t4 + 4];
            }
#pragma unroll
            for (int ni = 0; ni < 8; ni++) {
                int c = nbase + ni * 8 + g;
                bf[ni][0] = Bs[c * 36 + ks + t4];
                bf[ni][1] = Bs[c * 36 + ks + t4 + 4];
            }
#pragma unroll
            for (int mi = 0; mi < 2; mi++)
#pragma unroll
                for (int ni = 0; ni < 8; ni++)
                    mma_tf32(acc[mi][ni], af[mi], bf[ni]);
        }
        __syncthreads();
    }

    // epilogue: bias + relu + scatter to [B,512,N,T]
#pragma unroll
    for (int mi = 0; mi < 2; mi++) {
        int rloc = mbase + mi * 16 + g;
        int off0 = outOff[rloc];
        int off1 = outOff[rloc + 8];
#pragma unroll
        for (int ni = 0; ni < 8; ni++) {
            int j = nbase + ni * 8 + 2 * t4;
            int o = r0 + j;
            float b0 = bo[o], b1 = bo[o + 1];
            out[off0 + o * NTSTR]       = fmaxf(acc[mi][ni][0] + b0, 0.f);
            out[off0 + (o + 1) * NTSTR] = fmaxf(acc[mi][ni][1] + b1, 0.f);
            out[off1 + o * NTSTR]       = fmaxf(acc[mi][ni][2] + b0, 0.f);
            out[off1 + (o + 1) * NTSTR] = fmaxf(acc[mi][ni][3] + b1, 0.f);
        }
    }
}

// ---------------------------------------------------------------------------
extern "C" void kernel_launch(void* const* d_in, const int* in_sizes, int n_in,
                              void* d_out, int out_size)
{
    const float* x   = (const float*)d_in[0];
    const float* tem = (const float*)d_in[1];
    const float* Wq  = (const float*)d_in[2];
    const float* bq  = (const float*)d_in[3];
    const float* Wk  = (const float*)d_in[4];
    const float* bk  = (const float*)d_in[5];
    const float* Wv  = (const float*)d_in[6];
    const float* bv  = (const float*)d_in[7];
    const float* Wo  = (const float*)d_in[8];
    const float* bo  = (const float*)d_in[9];
    float* out = (float*)d_out;

    dim3 g1(BN / 2, 12);
    qkv_kernel<<<g1, 256>>>(x, tem, Wq, bq, Wk, bk, Wv, bv);

    attn_kernel<<<BN * NHEAD, 128>>>();

    dim3 g3(BN / 2, 4);
    out_kernel<<<g3, 256>>>(Wo, bo, out);
}

// round 4
// speedup vs baseline: 3.3595x; 3.3595x over previous
#include <cuda_runtime.h>
#include <cstdint>

// Problem constants (fixed shapes from setup_inputs)
#define BATCH   16
#define CHX     256
#define NPOS    170
#define TT      64
#define CIN     512
#define COUT    512
#define NHEAD   8
#define HDIM    64
#define BN      (BATCH*NPOS)      // 2720
#define NTSTR   (NPOS*TT)         // 10880 = channel stride in [B,C,N,T]
#define QKV_ELEMS (BN*NHEAD*TT*HDIM)   // 89,128,960

// Scratch (device globals — no allocation allowed)
__device__ float g_q[QKV_ELEMS];
__device__ float g_k[QKV_ELEMS];
__device__ float g_v[QKV_ELEMS];
__device__ float g_o[QKV_ELEMS];   // [token(174080)][512] row-major

// ---------------------------------------------------------------------------
__device__ __forceinline__ uint32_t f2tf32(float f) {
    uint32_t r;
    asm("cvt.rna.tf32.f32 %0, %1;" : "=r"(r) : "f"(f));
    return r;
}

__device__ __forceinline__ void mma_tf32(float* d, const uint32_t* a, const uint32_t* b) {
    asm volatile(
        "mma.sync.aligned.m16n8k8.row.col.f32.tf32.tf32.f32 "
        "{%0,%1,%2,%3},{%4,%5,%6,%7},{%8,%9},{%0,%1,%2,%3};\n"
        : "+f"(d[0]), "+f"(d[1]), "+f"(d[2]), "+f"(d[3])
        : "r"(a[0]), "r"(a[1]), "r"(a[2]), "r"(a[3]),
          "r"(b[0]), "r"(b[1]));
}

__device__ __forceinline__ void cpasync16(float* smem_dst, const float* gsrc) {
    uint32_t s = (uint32_t)__cvta_generic_to_shared(smem_dst);
    asm volatile("cp.async.cg.shared.global [%0], [%1], 16;\n"
                 :: "r"(s), "l"(gsrc) : "memory");
}
#define CP_COMMIT() asm volatile("cp.async.commit_group;\n" ::: "memory")
#define CP_WAIT2()  asm volatile("cp.async.wait_group 2;\n" ::: "memory")

// ---------------------------------------------------------------------------
// Kernel 1: QKV projection (3-stage cp.async pipeline).
// grid (1360, 12), block 256. Mtile=128 tokens, Ntile=128 outputs, Ktile=32.
// A stage: K-major [32][128 tokens], stride 136 (conflict-free frag loads,
//          t-contiguous gmem -> 16B cp.async chunks).
// B stage: [128][32], stride 36.
// ---------------------------------------------------------------------------
#define QK_SA    136
#define QK_SB    36
#define QK_AW    (32*QK_SA)          // 4352 words
#define QK_BW    (128*QK_SB)         // 4608 words
#define QK_STAGE (QK_AW+QK_BW)       // 8960 words
#define QK_SMEM  (3*QK_STAGE*4)      // 107520 bytes

__global__ __launch_bounds__(256, 2)
void qkv_kernel(const float* __restrict__ x, const float* __restrict__ tem,
                const float* __restrict__ Wq, const float* __restrict__ bq,
                const float* __restrict__ Wk, const float* __restrict__ bk,
                const float* __restrict__ Wv, const float* __restrict__ bv)
{
    extern __shared__ float sm[];

    const int tid = threadIdx.x;
    const int bn0 = blockIdx.x * 2;
    const int y   = blockIdx.y;

    const float* W;  const float* bias;  float* outBuf;
    const int mat = y >> 2;            // 0:q 1:k 2:v
    const int r0  = (y & 3) * 128;
    if (mat == 0)      { W = Wq; bias = bq; outBuf = g_q; }
    else if (mat == 1) { W = Wk; bias = bk; outBuf = g_k; }
    else               { W = Wv; bias = bv; outBuf = g_v; }

    // per-thread cp.async chunk metadata (4 A chunks + 4 B chunks)
    int kA[4], baseA[4], dstA[4], gB[4], dstB[4];
#pragma unroll
    for (int j = 0; j < 4; j++) {
        int cidx = tid + j * 256;              // 0..1023
        kA[j] = cidx >> 5;                     // k within tile 0..31
        int tc = cidx & 31;                    // token chunk 0..31 (4 tokens)
        int bn = bn0 + (tc >> 4);
        int b = bn / NPOS, n = bn % NPOS;
        baseA[j] = b * (CHX * NTSTR) + n * TT + (tc & 15) * 4;
        dstA[j]  = kA[j] * QK_SA + tc * 4;
        int nn = cidx >> 3, kc = cidx & 7;
        gB[j]   = (r0 + nn) * CIN + kc * 4;
        dstB[j] = nn * QK_SB + kc * 4;
    }

    const int lane = tid & 31, wid = tid >> 5;
    const int wm = wid & 3, wn = wid >> 2;
    const int g = lane >> 2, t4 = lane & 3;
    const int mbase = wm * 32, nbase = wn * 64;

    float acc[2][8][4];
#pragma unroll
    for (int mi = 0; mi < 2; mi++)
#pragma unroll
        for (int ni = 0; ni < 8; ni++)
#pragma unroll
            for (int j = 0; j < 4; j++) acc[mi][ni][j] = 0.f;

    auto issue = [&](int stage, int k0) {
        float* As = sm + stage * QK_STAGE;
        float* Bs = As + QK_AW;
#pragma unroll
        for (int j = 0; j < 4; j++) {
            int c = k0 + kA[j];
            const float* src = (c < CHX) ? (x + baseA[j] + c * NTSTR)
                                         : (tem + baseA[j] + (c - CHX) * NTSTR);
            cpasync16(As + dstA[j], src);
        }
#pragma unroll
        for (int j = 0; j < 4; j++)
            cpasync16(Bs + dstB[j], W + gB[j] + k0);
    };

    // prologue: fill all 3 stages
#pragma unroll
    for (int s = 0; s < 3; s++) { issue(s, s * 32); CP_COMMIT(); }

    for (int it = 0; it < 16; it++) {
        CP_WAIT2();
        __syncthreads();
        const int buf = it % 3;
        const float* As = sm + buf * QK_STAGE;
        const float* Bs = As + QK_AW;

#pragma unroll
        for (int ks = 0; ks < 32; ks += 8) {
            uint32_t af[2][4], bf[8][2];
#pragma unroll
            for (int mi = 0; mi < 2; mi++) {
                int r = mbase + mi * 16 + g;
                af[mi][0] = f2tf32(As[(ks + t4) * QK_SA + r]);
                af[mi][1] = f2tf32(As[(ks + t4) * QK_SA + r + 8]);
                af[mi][2] = f2tf32(As[(ks + t4 + 4) * QK_SA + r]);
                af[mi][3] = f2tf32(As[(ks + t4 + 4) * QK_SA + r + 8]);
            }
#pragma unroll
            for (int ni = 0; ni < 8; ni++) {
                int c = nbase + ni * 8 + g;
                bf[ni][0] = f2tf32(Bs[c * QK_SB + ks + t4]);
                bf[ni][1] = f2tf32(Bs[c * QK_SB + ks + t4 + 4]);
            }
#pragma unroll
            for (int mi = 0; mi < 2; mi++)
#pragma unroll
                for (int ni = 0; ni < 8; ni++)
                    mma_tf32(acc[mi][ni], af[mi], bf[ni]);
        }
        __syncthreads();
        int nx = it + 3;
        if (nx < 16) issue(buf, nx * 32);
        CP_COMMIT();
    }

    // Epilogue: bias + store into per-head [T,d] tiles
#pragma unroll
    for (int mi = 0; mi < 2; mi++) {
        int rloc = mbase + mi * 16 + g;
        int bn = bn0 + (rloc >> 6);
        int t  = rloc & 63;
        int tileBase = (bn * NHEAD) * (TT * HDIM);
#pragma unroll
        for (int ni = 0; ni < 8; ni++) {
            int j = nbase + ni * 8 + 2 * t4;
            int o = r0 + j;
            int h = o >> 6, dd = o & 63;
            float b0 = bias[o], b1 = bias[o + 1];
            float2 v0 = make_float2(acc[mi][ni][0] + b0, acc[mi][ni][1] + b1);
            float2 v1 = make_float2(acc[mi][ni][2] + b0, acc[mi][ni][3] + b1);
            int base = tileBase + h * (TT * HDIM) + dd;
            *(float2*)&outBuf[base + t * HDIM]       = v0;
            *(float2*)&outBuf[base + (t + 8) * HDIM] = v1;
        }
    }
}

// ---------------------------------------------------------------------------
// Kernel 2: causal attention per (bn, head) tile: [64,64] Q,K,V.
// grid 21760, block 128 (4 warps, each owns 16 rows x 64 cols).
// ---------------------------------------------------------------------------
__global__ __launch_bounds__(128, 4)
void attn_kernel()
{
    __shared__ uint32_t Qs[64 * 68];   // Q, then reused for P
    __shared__ uint32_t Ks[64 * 68];   // K, then reused for V^T

    const int tid = threadIdx.x;
    const int lane = tid & 31, wid = tid >> 5;
    const int g = lane >> 2, t4 = lane & 3;
    const int bh = blockIdx.x;
    const int base = bh * (TT * HDIM);

    for (int i = tid; i < TT * HDIM; i += 128) {
        int t = i >> 6, d = i & 63;
        Qs[t * 68 + d] = f2tf32(g_q[base + i]);
        Ks[t * 68 + d] = f2tf32(g_k[base + i]);
    }
    __syncthreads();

    const int rbase = wid * 16;
    float s[8][4];
#pragma unroll
    for (int ni = 0; ni < 8; ni++)
#pragma unroll
        for (int j = 0; j < 4; j++) s[ni][j] = 0.f;

#pragma unroll
    for (int ks = 0; ks < 64; ks += 8) {
        uint32_t af[4];
        int r = rbase + g;
        af[0] = Qs[r * 68 + ks + t4];
        af[1] = Qs[(r + 8) * 68 + ks + t4];
        af[2] = Qs[r * 68 + ks + t4 + 4];
        af[3] = Qs[(r + 8) * 68 + ks + t4 + 4];
#pragma unroll
        for (int ni = 0; ni < 8; ni++) {
            uint32_t bf[2];
            bf[0] = Ks[(ni * 8 + g) * 68 + ks + t4];
            bf[1] = Ks[(ni * 8 + g) * 68 + ks + t4 + 4];
            mma_tf32(s[ni], af, bf);
        }
    }
    __syncthreads();

    const int rA = rbase + g, rB = rA + 8;
    float mx0 = -1e30f, mx1 = -1e30f;
#pragma unroll
    for (int ni = 0; ni < 8; ni++) {
        int c0 = ni * 8 + 2 * t4, c1 = c0 + 1;
        s[ni][0] = (c0 <= rA) ? s[ni][0] * 0.125f : -32767.0f;
        s[ni][1] = (c1 <= rA) ? s[ni][1] * 0.125f : -32767.0f;
        s[ni][2] = (c0 <= rB) ? s[ni][2] * 0.125f : -32767.0f;
        s[ni][3] = (c1 <= rB) ? s[ni][3] * 0.125f : -32767.0f;
        mx0 = fmaxf(mx0, fmaxf(s[ni][0], s[ni][1]));
        mx1 = fmaxf(mx1, fmaxf(s[ni][2], s[ni][3]));
    }
    mx0 = fmaxf(mx0, __shfl_xor_sync(0xffffffffu, mx0, 1));
    mx0 = fmaxf(mx0, __shfl_xor_sync(0xffffffffu, mx0, 2));
    mx1 = fmaxf(mx1, __shfl_xor_sync(0xffffffffu, mx1, 1));
    mx1 = fmaxf(mx1, __shfl_xor_sync(0xffffffffu, mx1, 2));

    float sm0 = 0.f, sm1 = 0.f;
#pragma unroll
    for (int ni = 0; ni < 8; ni++) {
        s[ni][0] = __expf(s[ni][0] - mx0); sm0 += s[ni][0];
        s[ni][1] = __expf(s[ni][1] - mx0); sm0 += s[ni][1];
        s[ni][2] = __expf(s[ni][2] - mx1); sm1 += s[ni][2];
        s[ni][3] = __expf(s[ni][3] - mx1); sm1 += s[ni][3];
    }
    sm0 += __shfl_xor_sync(0xffffffffu, sm0, 1);
    sm0 += __shfl_xor_sync(0xffffffffu, sm0, 2);
    sm1 += __shfl_xor_sync(0xffffffffu, sm1, 1);
    sm1 += __shfl_xor_sync(0xffffffffu, sm1, 2);
    float inv0 = 1.f / sm0, inv1 = 1.f / sm1;

#pragma unroll
    for (int ni = 0; ni < 8; ni++) {
        int c0 = ni * 8 + 2 * t4;
        Qs[rA * 68 + c0]     = f2tf32(s[ni][0] * inv0);
        Qs[rA * 68 + c0 + 1] = f2tf32(s[ni][1] * inv0);
        Qs[rB * 68 + c0]     = f2tf32(s[ni][2] * inv1);
        Qs[rB * 68 + c0 + 1] = f2tf32(s[ni][3] * inv1);
    }
    for (int i = tid; i < TT * HDIM; i += 128) {
        int sidx = i >> 6, d = i & 63;
        Ks[d * 68 + sidx] = f2tf32(g_v[base + i]);
    }
    __syncthreads();

    float o[8][4];
#pragma unroll
    for (int ni = 0; ni < 8; ni++)
#pragma unroll
        for (int j = 0; j < 4; j++) o[ni][j] = 0.f;

#pragma unroll
    for (int ks = 0; ks < 64; ks += 8) {
        uint32_t af[4];
        int r = rbase + g;
        af[0] = Qs[r * 68 + ks + t4];
        af[1] = Qs[(r + 8) * 68 + ks + t4];
        af[2] = Qs[r * 68 + ks + t4 + 4];
        af[3] = Qs[(r + 8) * 68 + ks + t4 + 4];
#pragma unroll
        for (int ni = 0; ni < 8; ni++) {
            uint32_t bf[2];
            bf[0] = Ks[(ni * 8 + g) * 68 + ks + t4];
            bf[1] = Ks[(ni * 8 + g) * 68 + ks + t4 + 4];
            mma_tf32(o[ni], af, bf);
        }
    }

    const int bn = bh >> 3, h = bh & 7;
    float* ob = g_o + bn * (TT * COUT) + h * HDIM;
#pragma unroll
    for (int ni = 0; ni < 8; ni++) {
        int dd = ni * 8 + 2 * t4;
        *(float2*)&ob[rA * COUT + dd] = make_float2(o[ni][0], o[ni][1]);
        *(float2*)&ob[rB * COUT + dd] = make_float2(o[ni][2], o[ni][3]);
    }
}

// ---------------------------------------------------------------------------
// Kernel 3: output projection + bias + ReLU (3-stage cp.async pipeline).
// grid (1360, 4), block 256. Mtile=128 tokens, Ntile=128 outputs, Ktile=32.
// Both stages [row][k], stride 36 (k-contiguous gmem on both operands).
// ---------------------------------------------------------------------------
#define OP_S     36
#define OP_AW    (128*OP_S)          // 4608 words
#define OP_STAGE (2*OP_AW)           // 9216 words
#define OP_SMEM  (3*OP_STAGE*4)      // 110592 bytes

__global__ __launch_bounds__(256, 2)
void out_kernel(const float* __restrict__ Wo, const float* __restrict__ bo,
                float* __restrict__ out)
{
    extern __shared__ float sm[];
    __shared__ int outOff[128];

    const int tid = threadIdx.x;
    const int m0  = blockIdx.x * 128;
    const int r0  = blockIdx.y * 128;

    if (tid < 128) {
        int token = m0 + tid;
        int bn = token >> 6;
        int b = bn / NPOS, n = bn % NPOS;
        outOff[tid] = (b * COUT * NPOS + n) * TT + (token & 63);
    }

    int gA[4], dstA[4], gB[4], dstB[4];
#pragma unroll
    for (int j = 0; j < 4; j++) {
        int cidx = tid + j * 256;
        int m = cidx >> 3, kc = cidx & 7;
        gA[j]   = (m0 + m) * COUT + kc * 4;
        gB[j]   = (r0 + m) * COUT + kc * 4;
        dstA[j] = m * OP_S + kc * 4;
        dstB[j] = dstA[j];
    }

    const int lane = tid & 31, wid = tid >> 5;
    const int wm = wid & 3, wn = wid >> 2;
    const int g = lane >> 2, t4 = lane & 3;
    const int mbase = wm * 32, nbase = wn * 64;

    float acc[2][8][4];
#pragma unroll
    for (int mi = 0; mi < 2; mi++)
#pragma unroll
        for (int ni = 0; ni < 8; ni++)
#pragma unroll
            for (int j = 0; j < 4; j++) acc[mi][ni][j] = 0.f;

    auto issue = [&](int stage, int k0) {
        float* As = sm + stage * OP_STAGE;
        float* Bs = As + OP_AW;
#pragma unroll
        for (int j = 0; j < 4; j++)
            cpasync16(As + dstA[j], g_o + gA[j] + k0);
#pragma unroll
        for (int j = 0; j < 4; j++)
            cpasync16(Bs + dstB[j], Wo + gB[j] + k0);
    };

#pragma unroll
    for (int s = 0; s < 3; s++) { issue(s, s * 32); CP_COMMIT(); }

    for (int it = 0; it < 16; it++) {
        CP_WAIT2();
        __syncthreads();
        const int buf = it % 3;
        const float* As = sm + buf * OP_STAGE;
        const float* Bs = As + OP_AW;

#pragma unroll
        for (int ks = 0; ks < 32; ks += 8) {
            uint32_t af[2][4], bf[8][2];
#pragma unroll
            for (int mi = 0; mi < 2; mi++) {
                int r = mbase + mi * 16 + g;
                af[mi][0] = f2tf32(As[r * OP_S + ks + t4]);
                af[mi][1] = f2tf32(As[(r + 8) * OP_S + ks + t4]);
                af[mi][2] = f2tf32(As[r * OP_S + ks + t4 + 4]);
                af[mi][3] = f2tf32(As[(r + 8) * OP_S + ks + t4 + 4]);
            }
#pragma unroll
            for (int ni = 0; ni < 8; ni++) {
                int c = nbase + ni * 8 + g;
                bf[ni][0] = f2tf32(Bs[c * OP_S + ks + t4]);
                bf[ni][1] = f2tf32(Bs[c * OP_S + ks + t4 + 4]);
            }
#pragma unroll
            for (int mi = 0; mi < 2; mi++)
#pragma unroll
                for (int ni = 0; ni < 8; ni++)
                    mma_tf32(acc[mi][ni], af[mi], bf[ni]);
        }
        __syncthreads();
        int nx = it + 3;
        if (nx < 16) issue(buf, nx * 32);
        CP_COMMIT();
    }

    // epilogue: bias + relu + scatter to [B,512,N,T]
#pragma unroll
    for (int mi = 0; mi < 2; mi++) {
        int rloc = mbase + mi * 16 + g;
        int off0 = outOff[rloc];
        int off1 = outOff[rloc + 8];
#pragma unroll
        for (int ni = 0; ni < 8; ni++) {
            int j = nbase + ni * 8 + 2 * t4;
            int o = r0 + j;
            float b0 = bo[o], b1 = bo[o + 1];
            out[off0 + o * NTSTR]       = fmaxf(acc[mi][ni][0] + b0, 0.f);
            out[off0 + (o + 1) * NTSTR] = fmaxf(acc[mi][ni][1] + b1, 0.f);
            out[off1 + o * NTSTR]       = fmaxf(acc[mi][ni][2] + b0, 0.f);
            out[off1 + (o + 1) * NTSTR] = fmaxf(acc[mi][ni][3] + b1, 0.f);
        }
    }
}

// ---------------------------------------------------------------------------
extern "C" void kernel_launch(void* const* d_in, const int* in_sizes, int n_in,
                              void* d_out, int out_size)
{
    const float* x   = (const float*)d_in[0];
    const float* tem = (const float*)d_in[1];
    const float* Wq  = (const float*)d_in[2];
    const float* bq  = (const float*)d_in[3];
    const float* Wk  = (const float*)d_in[4];
    const float* bk  = (const float*)d_in[5];
    const float* Wv  = (const float*)d_in[6];
    const float* bv  = (const float*)d_in[7];
    const float* Wo  = (const float*)d_in[8];
    const float* bo  = (const float*)d_in[9];
    float* out = (float*)d_out;

    static bool attr_done = false;
    if (!attr_done) {
        cudaFuncSetAttribute(qkv_kernel, cudaFuncAttributeMaxDynamicSharedMemorySize, QK_SMEM);
        cudaFuncSetAttribute(out_kernel, cudaFuncAttributeMaxDynamicSharedMemorySize, OP_SMEM);
        attr_done = true;
    }

    dim3 g1(BN / 2, 12);
    qkv_kernel<<<g1, 256, QK_SMEM>>>(x, tem, Wq, bq, Wk, bk, Wv, bv);

    attn_kernel<<<BN * NHEAD, 128>>>();

    dim3 g3(BN / 2, 4);
    out_kernel<<<g3, 256, OP_SMEM>>>(Wo, bo, out);
}